// round 1
// baseline (speedup 1.0000x reference)
#include <cuda_runtime.h>

#define N_PTS   400000
#define NXY     468
#define CANVAS  (468 * 468)          // 219024
#define VXY     0.32f
#define VZf     6.0f
#define PCMINX  (-74.88f)
#define PCMINY  (-74.88f)
#define PCMINZ  (-2.0f)

// -------- scratch (static device globals; no allocations allowed) ----------
__device__ int   g_flat[N_PTS];
__device__ int   g_cnt[CANVAS];
__device__ float g_vsum[CANVAS * 3];
__device__ float g_v1[CANVAS * 64];     // 56 MB
__device__ float g_pf1[N_PTS * 64];     // 102 MB

// ---------------------------------------------------------------------------
// K0: zero cnt / vsum / v1 / out
// ---------------------------------------------------------------------------
__global__ void k_init(float* __restrict__ out) {
    int idx = blockIdx.x * blockDim.x + threadIdx.x;
    int stride = gridDim.x * blockDim.x;
    const int n4 = (CANVAS * 64) / 4;   // 3,504,384 float4
    float4 z = make_float4(0.f, 0.f, 0.f, 0.f);
    float4* o4 = (float4*)out;
    float4* v4 = (float4*)g_v1;
    for (int i = idx; i < n4; i += stride) {
        o4[i] = z;
        v4[i] = z;
    }
    for (int i = idx; i < CANVAS; i += stride) {
        g_cnt[i] = 0;
        g_vsum[3 * i + 0] = 0.f;
        g_vsum[3 * i + 1] = 0.f;
        g_vsum[3 * i + 2] = 0.f;
    }
}

// ---------------------------------------------------------------------------
// K1: per-point voxel index + count / xyz-sum scatter
// ---------------------------------------------------------------------------
__device__ __forceinline__ int voxel_coord(float v, float vmin, float vox, int nmax) {
    int c = (int)floorf(__fdiv_rn(v - vmin, vox));
    return min(max(c, 0), nmax - 1);
}

__global__ void k_scatter(const float* __restrict__ pts) {
    int i = blockIdx.x * blockDim.x + threadIdx.x;
    if (i >= N_PTS) return;
    float x = pts[i * 5 + 0];
    float y = pts[i * 5 + 1];
    float z = pts[i * 5 + 2];
    int cx = voxel_coord(x, PCMINX, VXY, NXY);
    int cy = voxel_coord(y, PCMINY, VXY, NXY);
    // NZ == 1: cz clamps to 0 always
    int flat = cy * NXY + cx;
    g_flat[i] = flat;
    atomicAdd(&g_cnt[flat], 1);
    atomicAdd(&g_vsum[3 * flat + 0], x);
    atomicAdd(&g_vsum[3 * flat + 1], y);
    atomicAdd(&g_vsum[3 * flat + 2], z);
}

// ---------------------------------------------------------------------------
// K2: per-point 11 features -> relu(f @ W1) -> store pf1, atomicMax into v1
// warp per point, lane handles outputs j = lane and lane+32
// ---------------------------------------------------------------------------
__global__ void k_pf1(const float* __restrict__ pts, const float* __restrict__ W1) {
    __shared__ float sW1[11 * 64];
    int tid = threadIdx.x;
    for (int i = tid; i < 11 * 64; i += 256) sW1[i] = W1[i];
    __syncthreads();

    int warp = tid >> 5;
    int lane = tid & 31;
    int i = blockIdx.x * 8 + warp;
    if (i >= N_PTS) return;

    float p0 = pts[i * 5 + 0];
    float p1 = pts[i * 5 + 1];
    float p2 = pts[i * 5 + 2];
    float p3 = pts[i * 5 + 3];
    float p4 = pts[i * 5 + 4];

    int flat = g_flat[i];
    float cnt = (float)g_cnt[flat];
    float inv = 1.0f / fmaxf(cnt, 1.0f);
    float mx = g_vsum[3 * flat + 0] * inv;
    float my = g_vsum[3 * flat + 1] * inv;
    float mz = g_vsum[3 * flat + 2] * inv;

    int cx = flat % NXY;
    int cy = flat / NXY;
    float cenx = (float)cx * VXY + (VXY * 0.5f + PCMINX);
    float ceny = (float)cy * VXY + (VXY * 0.5f + PCMINY);
    float cenz = (VZf * 0.5f + PCMINZ);   // cz == 0

    float f[11];
    f[0] = p0;  f[1] = p1;  f[2] = p2;  f[3] = p3;  f[4] = p4;
    f[5] = p0 - mx;   f[6] = p1 - my;   f[7] = p2 - mz;
    f[8] = p0 - cenx; f[9] = p1 - ceny; f[10] = p2 - cenz;

    float a0 = 0.f, a1 = 0.f;
    #pragma unroll
    for (int k = 0; k < 11; k++) {
        a0 = fmaf(f[k], sW1[k * 64 + lane], a0);
        a1 = fmaf(f[k], sW1[k * 64 + lane + 32], a1);
    }
    a0 = fmaxf(a0, 0.f);
    a1 = fmaxf(a1, 0.f);

    g_pf1[i * 64 + lane]      = a0;
    g_pf1[i * 64 + lane + 32] = a1;

    // relu output >= 0 and v1 initialized to 0 -> int atomicMax is valid and
    // reproduces where(occ, segment_max, 0) exactly.
    if (a0 > 0.f) atomicMax((int*)&g_v1[flat * 64 + lane],      __float_as_int(a0));
    if (a1 > 0.f) atomicMax((int*)&g_v1[flat * 64 + lane + 32], __float_as_int(a1));
}

// ---------------------------------------------------------------------------
// K3: pf2 = relu([pf1, v1[flat]] @ W2), scatter-max into out
// Tiled GEMM: 64 points x 64 outputs per block, K=128 in two 64-chunks.
// 256 threads, 4x4 register micro-tile per thread.
// ---------------------------------------------------------------------------
#define SA_LD 68   // padded A row stride (words) to avoid bank conflicts

__global__ void k_pf2(const float* __restrict__ W2, float* __restrict__ out) {
    __shared__ float sW[64 * 64];     // 16 KB, half of W2 at a time
    __shared__ float sA[64 * SA_LD];  // 17 KB

    int tid = threadIdx.x;
    int p0 = blockIdx.x * 64;
    int tx = tid & 15;        // output-col group
    int ty = tid >> 4;        // row group

    float acc[4][4];
    #pragma unroll
    for (int r = 0; r < 4; r++)
        #pragma unroll
        for (int c = 0; c < 4; c++) acc[r][c] = 0.f;

    // ---------- chunk 0: A = pf1 rows, W = W2[0:64,:] ----------
    for (int i = tid; i < 4096; i += 256) sW[i] = W2[i];
    {
        int r = tid >> 2, q = tid & 3;
        const float4* src = (const float4*)(g_pf1 + (long)(p0 + r) * 64);
        #pragma unroll
        for (int i = 0; i < 4; i++) {
            float4 v = src[q * 4 + i];
            *(float4*)&sA[r * SA_LD + (q * 4 + i) * 4] = v;
        }
    }
    __syncthreads();

    #pragma unroll 16
    for (int k = 0; k < 64; k++) {
        float4 b = *(const float4*)&sW[k * 64 + tx * 4];
        float a0 = sA[(ty * 4 + 0) * SA_LD + k];
        float a1 = sA[(ty * 4 + 1) * SA_LD + k];
        float a2 = sA[(ty * 4 + 2) * SA_LD + k];
        float a3 = sA[(ty * 4 + 3) * SA_LD + k];
        acc[0][0] = fmaf(a0, b.x, acc[0][0]); acc[0][1] = fmaf(a0, b.y, acc[0][1]);
        acc[0][2] = fmaf(a0, b.z, acc[0][2]); acc[0][3] = fmaf(a0, b.w, acc[0][3]);
        acc[1][0] = fmaf(a1, b.x, acc[1][0]); acc[1][1] = fmaf(a1, b.y, acc[1][1]);
        acc[1][2] = fmaf(a1, b.z, acc[1][2]); acc[1][3] = fmaf(a1, b.w, acc[1][3]);
        acc[2][0] = fmaf(a2, b.x, acc[2][0]); acc[2][1] = fmaf(a2, b.y, acc[2][1]);
        acc[2][2] = fmaf(a2, b.z, acc[2][2]); acc[2][3] = fmaf(a2, b.w, acc[2][3]);
        acc[3][0] = fmaf(a3, b.x, acc[3][0]); acc[3][1] = fmaf(a3, b.y, acc[3][1]);
        acc[3][2] = fmaf(a3, b.z, acc[3][2]); acc[3][3] = fmaf(a3, b.w, acc[3][3]);
    }
    __syncthreads();

    // ---------- chunk 1: A = v1[flat[row]], W = W2[64:128,:] ----------
    for (int i = tid; i < 4096; i += 256) sW[i] = W2[4096 + i];
    {
        int r = tid >> 2, q = tid & 3;
        int fl = g_flat[p0 + r];
        const float4* src = (const float4*)(g_v1 + (long)fl * 64);
        #pragma unroll
        for (int i = 0; i < 4; i++) {
            float4 v = src[q * 4 + i];
            *(float4*)&sA[r * SA_LD + (q * 4 + i) * 4] = v;
        }
    }
    __syncthreads();

    #pragma unroll 16
    for (int k = 0; k < 64; k++) {
        float4 b = *(const float4*)&sW[k * 64 + tx * 4];
        float a0 = sA[(ty * 4 + 0) * SA_LD + k];
        float a1 = sA[(ty * 4 + 1) * SA_LD + k];
        float a2 = sA[(ty * 4 + 2) * SA_LD + k];
        float a3 = sA[(ty * 4 + 3) * SA_LD + k];
        acc[0][0] = fmaf(a0, b.x, acc[0][0]); acc[0][1] = fmaf(a0, b.y, acc[0][1]);
        acc[0][2] = fmaf(a0, b.z, acc[0][2]); acc[0][3] = fmaf(a0, b.w, acc[0][3]);
        acc[1][0] = fmaf(a1, b.x, acc[1][0]); acc[1][1] = fmaf(a1, b.y, acc[1][1]);
        acc[1][2] = fmaf(a1, b.z, acc[1][2]); acc[1][3] = fmaf(a1, b.w, acc[1][3]);
        acc[2][0] = fmaf(a2, b.x, acc[2][0]); acc[2][1] = fmaf(a2, b.y, acc[2][1]);
        acc[2][2] = fmaf(a2, b.z, acc[2][2]); acc[2][3] = fmaf(a2, b.w, acc[2][3]);
        acc[3][0] = fmaf(a3, b.x, acc[3][0]); acc[3][1] = fmaf(a3, b.y, acc[3][1]);
        acc[3][2] = fmaf(a3, b.z, acc[3][2]); acc[3][3] = fmaf(a3, b.w, acc[3][3]);
    }

    // ---------- epilogue: relu + scatter atomicMax ----------
    #pragma unroll
    for (int r = 0; r < 4; r++) {
        int row = ty * 4 + r;
        int fl = g_flat[p0 + row];
        float* o = out + (long)fl * 64 + tx * 4;
        #pragma unroll
        for (int c = 0; c < 4; c++) {
            float v = fmaxf(acc[r][c], 0.f);
            if (v > 0.f) atomicMax((int*)&o[c], __float_as_int(v));
        }
    }
}

// ---------------------------------------------------------------------------
extern "C" void kernel_launch(void* const* d_in, const int* in_sizes, int n_in,
                              void* d_out, int out_size) {
    const float* points = (const float*)d_in[0];  // [400000, 5]
    const float* W1     = (const float*)d_in[1];  // [11, 64]
    const float* W2     = (const float*)d_in[2];  // [128, 64]
    float* out = (float*)d_out;                   // [219024, 64]

    k_init<<<4096, 256>>>(out);
    k_scatter<<<(N_PTS + 255) / 256, 256>>>(points);
    k_pf1<<<N_PTS / 8, 256>>>(points, W1);        // 50000 blocks, warp/point
    k_pf2<<<N_PTS / 64, 256>>>(W2, out);          // 6250 blocks
}